// round 2
// baseline (speedup 1.0000x reference)
#include <cuda_runtime.h>

// Adaptive avg pool (32,50,50,768) NHWC -> (32,7,7,768), fp32.
// Static geometry: all H/W windows are [7*o, 7*o+8) (size 8, stride 7).
// One CTA per (batch, oh): 4 h-groups x 192 channel-float4 lanes.
// R2 change: __launch_bounds__(768, 2) so all 224 CTAs are co-resident
// (2 CTAs/SM), eliminating the 1.51-wave tail that capped DRAM at 75.7%.

#define NB   32
#define HIN  50
#define WIN  50
#define CH   768
#define CV   192   // CH / 4 (float4 lanes)
#define HO   7
#define WO   7

static __device__ __forceinline__ void f4add(float4& a, const float4& v) {
    a.x += v.x; a.y += v.y; a.z += v.z; a.w += v.w;
}

__global__ __launch_bounds__(768, 2)
void adaptive_pool_kernel(const float4* __restrict__ in4, float4* __restrict__ out4) {
    __shared__ float4 buf[2][CV * WO];   // 2 * 192 * 7 * 16B = 43008 B

    const int bid  = blockIdx.x;         // 0..223
    const int b    = bid / HO;
    const int oh   = bid % HO;
    const int tid  = threadIdx.x;
    const int g    = tid / CV;           // h-group 0..3 (2 rows each)
    const int cvec = tid % CV;           // float4 channel lane
    const int h0   = oh * 7 + g * 2;     // window start + group offset

    float4 acc[WO];
    #pragma unroll
    for (int i = 0; i < WO; ++i) acc[i] = make_float4(0.f, 0.f, 0.f, 0.f);

    #pragma unroll
    for (int r = 0; r < 2; ++r) {
        const float4* row = in4 + ((size_t)((b * HIN) + h0 + r) * WIN) * CV + cvec;
        #pragma unroll
        for (int w = 0; w < WIN; ++w) {
            float4 v = row[(size_t)w * CV];
            int owa = w / 7; if (owa > 6) owa = 6;   // compile-time under unroll
            f4add(acc[owa], v);
            if ((w % 7 == 0) && (w > 0) && (w < 49)) {
                f4add(acc[w / 7 - 1], v);            // boundary col in two windows
            }
        }
    }

    // Tree reduction over the 4 h-groups.
    if (g >= 2) {
        float4* dst = buf[g - 2];
        #pragma unroll
        for (int i = 0; i < WO; ++i) dst[i * CV + cvec] = acc[i];
    }
    __syncthreads();
    if (g < 2) {
        const float4* src = buf[g];
        #pragma unroll
        for (int i = 0; i < WO; ++i) f4add(acc[i], src[i * CV + cvec]);
    }
    __syncthreads();
    if (g == 1) {
        #pragma unroll
        for (int i = 0; i < WO; ++i) buf[0][i * CV + cvec] = acc[i];
    }
    __syncthreads();
    if (g == 0) {
        #pragma unroll
        for (int i = 0; i < WO; ++i) f4add(acc[i], buf[0][i * CV + cvec]);

        const float s = 1.0f / 64.0f;   // 8x8 window
        float4* o = out4 + ((size_t)(b * HO + oh) * WO) * CV + cvec;
        #pragma unroll
        for (int ow = 0; ow < WO; ++ow) {
            float4 rr = acc[ow];
            rr.x *= s; rr.y *= s; rr.z *= s; rr.w *= s;
            o[(size_t)ow * CV] = rr;
        }
    }
}

extern "C" void kernel_launch(void* const* d_in, const int* in_sizes, int n_in,
                              void* d_out, int out_size) {
    const float4* in4 = (const float4*)d_in[0];
    float4* out4 = (float4*)d_out;
    adaptive_pool_kernel<<<NB * HO, 768>>>(in4, out4);
}

// round 3
// speedup vs baseline: 1.3535x; 1.3535x over previous
#include <cuda_runtime.h>

// Adaptive avg pool (32,50,50,768) NHWC -> (32,7,7,768), fp32.
// All H/W windows are [7*o, 7*o+8) (size 8, stride 7), avg over 64 elems.
//
// R3: flat mapping — one thread per output float4. 301,056 threads total
// (~= chip capacity 148*2048), 64-thread CTAs, grid 4704 <= 4736 slots ->
// single wave. One accumulator per thread; __launch_bounds__(64,32) caps
// regs at 32 so all 32 CTAs/SM are resident. 64 independent LDG.128 per
// thread provide the MLP; 64 warps/SM provide latency hiding.

#define HIN  50
#define WIN  50
#define CV   192   // 768 / 4 float4 lanes per pixel
#define HO   7
#define WO   7

__global__ __launch_bounds__(64, 32)
void adaptive_pool_flat(const float4* __restrict__ in4, float4* __restrict__ out4) {
    // bid = ((b*7 + oh)*7 + ow)*3 + cseg ; lane = threadIdx.x (0..63)
    const int bid  = blockIdx.x;
    const int cseg = bid % 3;
    const int t    = bid / 3;          // 0..1567 = (b*7+oh)*7+ow
    const int ow   = t % WO;
    const int u    = t / WO;           // b*7+oh
    const int oh   = u % HO;
    const int b    = u / HO;
    const int cvec = cseg * 64 + threadIdx.x;

    const int h0 = oh * 7;
    const int w0 = ow * 7;

    float4 acc = make_float4(0.f, 0.f, 0.f, 0.f);

    const float4* base = in4 + ((size_t)(b * HIN + h0) * WIN + w0) * CV + cvec;

    #pragma unroll
    for (int r = 0; r < 8; ++r) {
        const float4* row = base + (size_t)r * (WIN * CV);
        #pragma unroll
        for (int c = 0; c < 8; ++c) {
            float4 v = row[(size_t)c * CV];
            acc.x += v.x; acc.y += v.y; acc.z += v.z; acc.w += v.w;
        }
    }

    const float s = 1.0f / 64.0f;
    acc.x *= s; acc.y *= s; acc.z *= s; acc.w *= s;
    out4[(size_t)t * CV + cvec] = acc;
}

extern "C" void kernel_launch(void* const* d_in, const int* in_sizes, int n_in,
                              void* d_out, int out_size) {
    const float4* in4 = (const float4*)d_in[0];
    float4* out4 = (float4*)d_out;
    adaptive_pool_flat<<<32 * HO * WO * 3, 64>>>(in4, out4);
}

// round 4
// speedup vs baseline: 1.4732x; 1.0885x over previous
#include <cuda_runtime.h>

// Adaptive avg pool (32,50,50,768) NHWC -> (32,7,7,768), fp32.
// All H/W windows are [7*o, 7*o+8) (size 8, stride 7), avg over 64 elems.
//
// R4: R3 flat mapping (one thread per output float4, 4704 CTAs x 64 thr,
// single wave, 32 regs) + boundary-aware row ordering. Rows are visited in
// order {7,0,1..6} so the H-shared boundary rows (read by two adjacent-oh
// CTAs) are touched at nearly the same time by both sharers -> L2 dedup
// instead of a second DRAM fetch (-29.5 MB DRAM traffic). Interior rows
// (r=1..6, read exactly once) use __ldcs streaming loads so they don't
// evict the boundary lines from L2.

#define HIN  50
#define WIN  50
#define CV   192   // 768 / 4 float4 lanes per pixel
#define HO   7
#define WO   7

__global__ __launch_bounds__(64, 32)
void adaptive_pool_flat(const float4* __restrict__ in4, float4* __restrict__ out4) {
    // bid = ((b*7 + oh)*7 + ow)*3 + cseg ; lane = threadIdx.x (0..63)
    const int bid  = blockIdx.x;
    const int cseg = bid % 3;
    const int t    = bid / 3;          // 0..1567 = (b*7+oh)*7+ow
    const int ow   = t % WO;
    const int u    = t / WO;           // b*7+oh
    const int oh   = u % HO;
    const int b    = u / HO;
    const int cvec = cseg * 64 + threadIdx.x;

    const int h0 = oh * 7;
    const int w0 = ow * 7;

    float4 acc = make_float4(0.f, 0.f, 0.f, 0.f);

    const float4* base = in4 + ((size_t)(b * HIN + h0) * WIN + w0) * CV + cvec;

    // Row visit order: boundary rows first (7 then 0), interior after.
    const int rorder[8] = {7, 0, 1, 2, 3, 4, 5, 6};

    #pragma unroll
    for (int i = 0; i < 8; ++i) {
        const int r = rorder[i];
        const float4* row = base + (size_t)r * (WIN * CV);
        const bool boundary = (r == 0) || (r == 7);
        #pragma unroll
        for (int c = 0; c < 8; ++c) {
            float4 v;
            if (boundary) {
                v = row[(size_t)c * CV];                 // default: keep in L2
            } else {
                v = __ldcs(&row[(size_t)c * CV]);        // streaming: evict-first
            }
            acc.x += v.x; acc.y += v.y; acc.z += v.z; acc.w += v.w;
        }
    }

    const float s = 1.0f / 64.0f;
    acc.x *= s; acc.y *= s; acc.z *= s; acc.w *= s;
    out4[(size_t)t * CV + cvec] = acc;
}

extern "C" void kernel_launch(void* const* d_in, const int* in_sizes, int n_in,
                              void* d_out, int out_size) {
    const float4* in4 = (const float4*)d_in[0];
    float4* out4 = (float4*)d_out;
    adaptive_pool_flat<<<32 * HO * WO * 3, 64>>>(in4, out4);
}

// round 5
// speedup vs baseline: 1.4901x; 1.0115x over previous
#include <cuda_runtime.h>

// Adaptive avg pool (32,50,50,768) NHWC -> (32,7,7,768), fp32.
// All H/W windows are [7*o, 7*o+8) (size 8, stride 7), avg over 64 elems.
//
// R5: R4 scheme (one thread per output float4, single wave, 32 regs,
// boundary-rows-first ordering, __ldcs streaming interior) with 4x fewer,
// 4x larger CTAs: 1176 CTAs x 256 threads <= 148 SMs x 8 CTAs -> still a
// single wave, less dispatch overhead, 4KB-contiguous per-step footprint.

#define HIN  50
#define WIN  50
#define CV   192   // 768 / 4 float4 lanes per pixel
#define HO   7
#define WO   7

__global__ __launch_bounds__(256, 8)
void adaptive_pool_flat(const float4* __restrict__ in4, float4* __restrict__ out4) {
    // virtual 64-thread group id: 4 per CTA
    const int virt = blockIdx.x * 4 + (threadIdx.x >> 6);  // 0..4703
    const int lane = threadIdx.x & 63;
    const int cseg = virt % 3;
    const int t    = virt / 3;          // 0..1567 = (b*7+oh)*7+ow
    const int ow   = t % WO;
    const int u    = t / WO;            // b*7+oh
    const int oh   = u % HO;
    const int b    = u / HO;
    const int cvec = cseg * 64 + lane;

    const int h0 = oh * 7;
    const int w0 = ow * 7;

    float4 acc = make_float4(0.f, 0.f, 0.f, 0.f);

    const float4* base = in4 + ((size_t)(b * HIN + h0) * WIN + w0) * CV + cvec;

    // Boundary rows first (7 then 0): shared with adjacent-oh windows, both
    // sharers touch them at nearly the same time -> L2 dedup. Default policy
    // keeps them L2-resident.
    #pragma unroll
    for (int c = 0; c < 8; ++c) {
        float4 v = base[(size_t)(7 * WIN + c) * CV];
        acc.x += v.x; acc.y += v.y; acc.z += v.z; acc.w += v.w;
    }
    #pragma unroll
    for (int c = 0; c < 8; ++c) {
        float4 v = base[(size_t)c * CV];
        acc.x += v.x; acc.y += v.y; acc.z += v.z; acc.w += v.w;
    }

    // Interior rows 1..6: read exactly once chip-wide -> streaming loads.
    #pragma unroll
    for (int r = 1; r < 7; ++r) {
        const float4* row = base + (size_t)r * (WIN * CV);
        #pragma unroll
        for (int c = 0; c < 8; ++c) {
            float4 v = __ldcs(&row[(size_t)c * CV]);
            acc.x += v.x; acc.y += v.y; acc.z += v.z; acc.w += v.w;
        }
    }

    const float s = 1.0f / 64.0f;
    acc.x *= s; acc.y *= s; acc.z *= s; acc.w *= s;
    out4[(size_t)t * CV + cvec] = acc;
}

extern "C" void kernel_launch(void* const* d_in, const int* in_sizes, int n_in,
                              void* d_out, int out_size) {
    const float4* in4 = (const float4*)d_in[0];
    float4* out4 = (float4*)d_out;
    adaptive_pool_flat<<<(32 * HO * WO * 3) / 4, 256>>>(in4, out4);
}